// round 1
// baseline (speedup 1.0000x reference)
#include <cuda_runtime.h>
#include <cstdint>

// LatticeSnake: B=32, L=512, W=9. Output [B, L, 9,9,9, 1] fp32.
// Per residue i: scatter-add every snake point (residue or bond midpoint)
// falling in the 9^3 window centered at its (doubled) lattice coordinate.
// Works entirely in doubled walk coords (the 2*(L-1) grid offset cancels):
//   residue j:   p = 2*idx[j],            v = acids[j]*mask[j]
//   midpoint j:  p = idx[j]+idx[j+1],     v = (acids[j]+acids[j+1]+1)*mask[j+1]
//   window r:    rel = p - 2*idx[r] + 4,  valid iff all rel in [0, 8]
//   lin = (rel0*9 + rel1)*9 + rel2

#define LS_L   512
#define LS_W   9
#define LS_W3  729
#define LS_R   8              // residues (windows) per CTA
#define LS_NT  256            // threads per CTA
#define LS_NG  (LS_L / LS_R)  // 64 residue-groups per batch

__global__ __launch_bounds__(LS_NT, 6)
void lattice_snake_kernel(const float* __restrict__ acids,
                          const float* __restrict__ mask,
                          const int*   __restrict__ idx,
                          float*       __restrict__ out)
{
    __shared__ float win[LS_R * LS_W3];   // 23328 B, 8 windows
    __shared__ int   sidx[LS_L * 3];      // 6144 B  (x,y,z interleaved, stride 3)
    __shared__ float sA[LS_L];            // 2048 B
    __shared__ float sM[LS_L];            // 2048 B

    const int b   = blockIdx.x >> 6;          // / LS_NG
    const int g   = blockIdx.x & (LS_NG - 1);
    const int i0  = g * LS_R;
    const int tid = threadIdx.x;

    // ---- stage this batch's inputs (L2-hot after first CTA touches them) ----
    const int*   gi = idx   + (size_t)b * LS_L * 3;
    const float* ga = acids + (size_t)b * LS_L;
    const float* gm = mask  + (size_t)b * LS_L;

    #pragma unroll
    for (int e = tid; e < LS_L * 3; e += LS_NT) sidx[e] = gi[e];
    for (int e = tid; e < LS_L;     e += LS_NT) { sA[e] = ga[e]; sM[e] = gm[e]; }

    // ---- zero the 8 windows (5832 floats = 1458 float4, exact) ----
    {
        float4* w4 = reinterpret_cast<float4*>(win);
        const float4 z = make_float4(0.f, 0.f, 0.f, 0.f);
        #pragma unroll
        for (int e = tid; e < (LS_R * LS_W3) / 4; e += LS_NT) w4[e] = z;
    }
    __syncthreads();

    // ---- window centers (doubled coords) + group bounding box for pruning ----
    int cx[LS_R], cy[LS_R], cz[LS_R];
    int xmin =  0x7fffffff, ymin =  0x7fffffff, zmin =  0x7fffffff;
    int xmax = -0x7fffffff, ymax = -0x7fffffff, zmax = -0x7fffffff;
    #pragma unroll
    for (int r = 0; r < LS_R; r++) {
        const int jj = 3 * (i0 + r);
        const int x = 2 * sidx[jj + 0];
        const int y = 2 * sidx[jj + 1];
        const int z = 2 * sidx[jj + 2];
        cx[r] = x; cy[r] = y; cz[r] = z;
        xmin = min(xmin, x); xmax = max(xmax, x);
        ymin = min(ymin, y); ymax = max(ymax, y);
        zmin = min(zmin, z); zmax = max(zmax, z);
    }
    // point p can only hit a window if within [c-4, c+4] of some center
    xmin -= 4; xmax += 4; ymin -= 4; ymax += 4; zmin -= 4; zmax += 4;

    // ---- main loop over all M = 2L-1 = 1023 snake points ----
    const int M = 2 * LS_L - 1;
    for (int j = tid; j < M; j += LS_NT) {
        int px, py, pz; float v;
        if (j < LS_L) {
            const int jj = 3 * j;
            px = 2 * sidx[jj + 0];
            py = 2 * sidx[jj + 1];
            pz = 2 * sidx[jj + 2];
            v  = sA[j] * sM[j];
        } else {
            const int k  = j - LS_L;          // 0 .. L-2
            const int jj = 3 * k;
            px = sidx[jj + 0] + sidx[jj + 3];
            py = sidx[jj + 1] + sidx[jj + 4];
            pz = sidx[jj + 2] + sidx[jj + 5];
            v  = (sA[k] + sA[k + 1] + 1.0f) * sM[k + 1];
        }

        // bbox prune: rejects the large majority of the 1023 points
        if (px < xmin || px > xmax ||
            py < ymin || py > ymax ||
            pz < zmin || pz > zmax) continue;

        #pragma unroll
        for (int r = 0; r < LS_R; r++) {
            const unsigned rx = (unsigned)(px - cx[r] + 4);
            const unsigned ry = (unsigned)(py - cy[r] + 4);
            const unsigned rz = (unsigned)(pz - cz[r] + 4);
            if (rx <= 8u && ry <= 8u && rz <= 8u) {
                const int lin = (int)((rx * LS_W + ry) * LS_W + rz);
                atomicAdd(&win[r * LS_W3 + lin], v);
            }
        }
    }
    __syncthreads();

    // ---- coalesced write: 8*729 = 5832 contiguous floats per CTA ----
    // base element index = (b*512 + i0)*729, i0 % 8 == 0 -> 32B aligned.
    {
        const float4* w4 = reinterpret_cast<const float4*>(win);
        float4* o4 = reinterpret_cast<float4*>(out + (size_t)(b * LS_L + i0) * LS_W3);
        #pragma unroll
        for (int e = tid; e < (LS_R * LS_W3) / 4; e += LS_NT) o4[e] = w4[e];
    }
}

extern "C" void kernel_launch(void* const* d_in, const int* in_sizes, int n_in,
                              void* d_out, int out_size)
{
    const float* acids = (const float*)d_in[0];   // [B, L]
    const float* mask  = (const float*)d_in[1];   // [B, L]
    const int*   idx   = (const int*)  d_in[2];   // [B, L, 3]
    float*       out   = (float*)d_out;           // [B, L, 9,9,9, 1]

    const int nB = in_sizes[0] / LS_L;            // 32
    lattice_snake_kernel<<<nB * LS_NG, LS_NT>>>(acids, mask, idx, out);
}

// round 2
// speedup vs baseline: 1.4140x; 1.4140x over previous
#include <cuda_runtime.h>
#include <cstdint>

// LatticeSnake: B=32, L=512, W=9. Output [B, L, 9,9,9, 1] fp32.
// Doubled walk coords (grid offset cancels):
//   residue j:   p = 2*idx[j],            v = acids[j]*mask[j]
//   midpoint j:  p = idx[j]+idx[j+1],     v = (acids[j]+acids[j+1]+1)*mask[j+1]
//   window r:    rel = p - 2*idx[r] + 4,  valid iff all rel in [0,8]
//
// R2 design: no smem window accumulator. Each CTA owns 8 consecutive windows:
//   phase 1: STG.128 zero-fill its contiguous 23.3KB output slice (L2-resident)
//   phase 2: loop all 1023 snake points, bbox-prune, RED.ADD.F32 the few real
//            hits straight to global (L2 atomics, ~0.85 cyc/lane, no ATOMS
//            32cyc/warp serialization, no 2x23KB smem roundtrip).

#define LS_L   512
#define LS_W   9
#define LS_W3  729
#define LS_R   8              // windows per CTA
#define LS_NT  256
#define LS_NG  (LS_L / LS_R)  // 64

__global__ __launch_bounds__(LS_NT)
void lattice_snake_kernel(const float* __restrict__ acids,
                          const float* __restrict__ mask,
                          const int*   __restrict__ idx,
                          float*       __restrict__ out)
{
    __shared__ int scen[LS_R * 3];   // doubled coords of the 8 window centers

    const int b   = blockIdx.x >> 6;           // / LS_NG
    const int g   = blockIdx.x & (LS_NG - 1);
    const int i0  = g * LS_R;
    const int tid = threadIdx.x;

    const int*   gi = idx   + (size_t)b * LS_L * 3;
    const float* ga = acids + (size_t)b * LS_L;
    const float* gm = mask  + (size_t)b * LS_L;
    float* gout = out + (size_t)(b * LS_L + i0) * LS_W3;

    // stage the 8 window centers (24 ints)
    if (tid < LS_R * 3) scen[tid] = 2 * gi[3 * i0 + tid];

    // ---- phase 1: zero-fill our contiguous output slice (1458 float4) ----
    {
        float4* o4 = reinterpret_cast<float4*>(gout);
        const float4 z = make_float4(0.f, 0.f, 0.f, 0.f);
        #pragma unroll
        for (int e = tid; e < (LS_R * LS_W3) / 4; e += LS_NT) o4[e] = z;
    }
    __syncthreads();   // orders zero-fill STGs before any RED from this CTA

    // centers -> registers, plus group bbox (+/- window radius 4)
    int cx[LS_R], cy[LS_R], cz[LS_R];
    int xmin =  0x7fffffff, ymin =  0x7fffffff, zmin =  0x7fffffff;
    int xmax = -0x7fffffff, ymax = -0x7fffffff, zmax = -0x7fffffff;
    #pragma unroll
    for (int r = 0; r < LS_R; r++) {
        const int x = scen[3 * r + 0];
        const int y = scen[3 * r + 1];
        const int z = scen[3 * r + 2];
        cx[r] = x; cy[r] = y; cz[r] = z;
        xmin = min(xmin, x); xmax = max(xmax, x);
        ymin = min(ymin, y); ymax = max(ymax, y);
        zmin = min(zmin, z); zmax = max(zmax, z);
    }
    xmin -= 4; xmax += 4; ymin -= 4; ymax += 4; zmin -= 4; zmax += 4;

    // ---- phase 2: all M = 1023 snake points, scatter real hits via RED ----
    const int M = 2 * LS_L - 1;
    for (int j = tid; j < M; j += LS_NT) {
        int px, py, pz; float v;
        if (j < LS_L) {
            const int jj = 3 * j;
            px = 2 * gi[jj + 0];
            py = 2 * gi[jj + 1];
            pz = 2 * gi[jj + 2];
            v  = ga[j] * gm[j];
        } else {
            const int k  = j - LS_L;          // 0 .. L-2
            const int jj = 3 * k;
            px = gi[jj + 0] + gi[jj + 3];
            py = gi[jj + 1] + gi[jj + 4];
            pz = gi[jj + 2] + gi[jj + 5];
            v  = (ga[k] + ga[k + 1] + 1.0f) * gm[k + 1];
        }

        if (px < xmin || px > xmax ||
            py < ymin || py > ymax ||
            pz < zmin || pz > zmax) continue;

        #pragma unroll
        for (int r = 0; r < LS_R; r++) {
            const unsigned rx = (unsigned)(px - cx[r] + 4);
            const unsigned ry = (unsigned)(py - cy[r] + 4);
            const unsigned rz = (unsigned)(pz - cz[r] + 4);
            if (rx <= 8u && ry <= 8u && rz <= 8u) {
                const int lin = (int)((rx * LS_W + ry) * LS_W + rz);
                atomicAdd(&gout[r * LS_W3 + lin], v);   // return unused -> RED.ADD
            }
        }
    }
}

extern "C" void kernel_launch(void* const* d_in, const int* in_sizes, int n_in,
                              void* d_out, int out_size)
{
    const float* acids = (const float*)d_in[0];   // [B, L]
    const float* mask  = (const float*)d_in[1];   // [B, L]
    const int*   idx   = (const int*)  d_in[2];   // [B, L, 3]
    float*       out   = (float*)d_out;           // [B, L, 9,9,9, 1]

    const int nB = in_sizes[0] / LS_L;            // 32
    lattice_snake_kernel<<<nB * LS_NG, LS_NT>>>(acids, mask, idx, out);
}